// round 3
// baseline (speedup 1.0000x reference)
#include <cuda_runtime.h>

#define NN    512
#define H     128
#define L     4
#define NRBF  50
#define TBL   8192
#define NMOL  16
#define JT    4     // target nodes per msg block
#define IS    4     // i-range splits (for grid occupancy)
#define NT    4     // nodes per update block

// ---- scratch (static __device__, no allocation) ----
__device__ float4 g_geo[NN * NN];            // [j][i] = (d_or_1e9, dirx, diry, dirz)
__device__ float  g_tbl[L][TBL + 1][H];      // psi_l(d) = rbf(d) @ Wr_l, tabulated
__device__ float  g_x[NN * H];
__device__ float  g_A[NN * H];               // x @ Wx + b1
__device__ float  g_S[NN * H];               // sum_i silu(pre[i,j])
__device__ float  g_cnt[NN];                 // # valid neighbors of j

__device__ __forceinline__ float siluf(float v) {
    return v * __fdividef(1.0f, 1.0f + __expf(-v));
}

// x = embed[clip(atomic_numbers)]
__global__ void k_embed(const int* __restrict__ an, const float* __restrict__ embed) {
    int i = blockIdx.x, h = threadIdx.x;
    int a = an[i];
    a = a < 0 ? 0 : (a > 99 ? 99 : a);
    g_x[i * H + h] = embed[a * H + h];
}

// pair geometry: distance gate + unit directions. dir[i,j] = (p_i - p_j)/max(d,1e-8)
__global__ void k_geo(const float* __restrict__ pos) {
    int t = blockIdx.x * blockDim.x + threadIdx.x;
    if (t >= NN * NN) return;
    int j = t / NN, i = t % NN;
    float dx = pos[i * 3 + 0] - pos[j * 3 + 0];
    float dy = pos[i * 3 + 1] - pos[j * 3 + 1];
    float dz = pos[i * 3 + 2] - pos[j * 3 + 2];
    float d  = sqrtf(dx * dx + dy * dy + dz * dz);
    float dm = fmaxf(d, 1e-8f);
    float inv = 1.0f / dm;
    bool valid = (d < 5.0f) && (i != j);
    g_geo[t] = make_float4(valid ? d : 1e9f, dx * inv, dy * inv, dz * inv);
}

// build psi tables: psi_l(d_idx)[h] = sum_k exp(-50*(d-c_k)^2) * Wr_l[k,h]
__global__ void k_table(const float* __restrict__ msg_w1) {
    int idx = blockIdx.x;           // 0..TBL
    int l   = blockIdx.y;
    int h   = threadIdx.x;
    __shared__ float e[NRBF];
    float d = 5.0f * (float)idx / (float)TBL;
    if (h < NRBF) {
        float c = 5.0f * (float)h / (float)(NRBF - 1);
        float u = d - c;
        e[h] = expf(-u * u * 50.0f);
    }
    __syncthreads();
    const float* Wr = msg_w1 + l * 181 * H + H * H;   // rows [H, H+50)
    float s = 0.0f;
#pragma unroll
    for (int k = 0; k < NRBF; k++)
        s = fmaf(e[k], Wr[k * H + h], s);
    g_tbl[l][idx][h] = s;
}

// A = x @ Wx_l + b1_l ; also zero S and cnt for this layer
__global__ void k_A(const float* __restrict__ msg_w1, const float* __restrict__ msg_b1, int l) {
    int i = blockIdx.x, h = threadIdx.x;
    __shared__ float xv[H];
    xv[h] = g_x[i * H + h];
    __syncthreads();
    const float* Wx = msg_w1 + l * 181 * H;           // rows [0, H)
    float acc = msg_b1[l * H + h];
#pragma unroll 8
    for (int k = 0; k < H; k++)
        acc = fmaf(xv[k], Wx[k * H + h], acc);
    g_A[i * H + h] = acc;
    g_S[i * H + h] = 0.0f;
    if (h == 0) g_cnt[i] = 0.0f;
}

// message pass: S[j,h] = sum_{i valid} silu(A[i,h] + psi_l(d_ij)[h] + dir_ij . Wd[:,h])
__global__ void k_msg(const float* __restrict__ msg_w1, int l) {
    int j0 = blockIdx.x * JT;
    int i0 = blockIdx.y * (NN / IS);
    int h  = threadIdx.x;
    const float* Wd = msg_w1 + l * 181 * H + (H + NRBF) * H;  // rows [H+50, H+53)
    float wd0 = Wd[0 * H + h], wd1 = Wd[1 * H + h], wd2 = Wd[2 * H + h];
    const float* tbl = &g_tbl[l][0][0];

    float acc[JT], cf[JT];
#pragma unroll
    for (int jj = 0; jj < JT; jj++) { acc[jj] = 0.0f; cf[jj] = 0.0f; }

    for (int i = i0; i < i0 + NN / IS; i++) {
        float a = g_A[i * H + h];
#pragma unroll
        for (int jj = 0; jj < JT; jj++) {
            float4 w = g_geo[(j0 + jj) * NN + i];   // uniform across block (broadcast)
            if (w.x < 5.0f) {                        // uniform branch
                float t  = w.x * ((float)TBL / 5.0f);
                int   t0 = (int)t;
                float f  = t - (float)t0;
                float T0 = tbl[t0 * H + h];
                float T1 = tbl[t0 * H + H + h];
                float pre = a + T0 + f * (T1 - T0);
                pre = fmaf(w.y, wd0, pre);
                pre = fmaf(w.z, wd1, pre);
                pre = fmaf(w.w, wd2, pre);
                acc[jj] += siluf(pre);
                cf[jj]  += 1.0f;
            }
        }
    }
#pragma unroll
    for (int jj = 0; jj < JT; jj++) {
        atomicAdd(&g_S[(j0 + jj) * H + h], acc[jj]);
        if (h == 0) atomicAdd(&g_cnt[j0 + jj], cf[jj]);
    }
}

// aggr = S@W2 + cnt*b2 ; x += silu([x,aggr]@U1 + ub1) @ U2 + ub2
__global__ void k_upd(const float* __restrict__ msg_w2, const float* __restrict__ msg_b2,
                      const float* __restrict__ upd_w1, const float* __restrict__ upd_b1,
                      const float* __restrict__ upd_w2, const float* __restrict__ upd_b2, int l) {
    int j0 = blockIdx.x * NT;
    int h  = threadIdx.x;
    __shared__ float sv[NT][H], xv[NT][H], av[NT][H], hv[NT][H];
#pragma unroll
    for (int jj = 0; jj < NT; jj++) {
        sv[jj][h] = g_S[(j0 + jj) * H + h];
        xv[jj][h] = g_x[(j0 + jj) * H + h];
    }
    __syncthreads();
    {   // aggr = S @ W2 + cnt * b2
        float b = msg_b2[l * H + h];
        float acc[NT];
#pragma unroll
        for (int jj = 0; jj < NT; jj++) acc[jj] = g_cnt[j0 + jj] * b;
        const float* W2 = msg_w2 + l * H * H;
#pragma unroll 4
        for (int k = 0; k < H; k++) {
            float w = W2[k * H + h];
#pragma unroll
            for (int jj = 0; jj < NT; jj++) acc[jj] = fmaf(sv[jj][k], w, acc[jj]);
        }
#pragma unroll
        for (int jj = 0; jj < NT; jj++) av[jj][h] = acc[jj];
    }
    __syncthreads();
    {   // hv = silu([x, aggr] @ U1 + ub1)
        float acc[NT];
        float b = upd_b1[l * H + h];
#pragma unroll
        for (int jj = 0; jj < NT; jj++) acc[jj] = b;
        const float* U1 = upd_w1 + l * 2 * H * H;
#pragma unroll 4
        for (int k = 0; k < H; k++) {
            float w = U1[k * H + h];
#pragma unroll
            for (int jj = 0; jj < NT; jj++) acc[jj] = fmaf(xv[jj][k], w, acc[jj]);
        }
#pragma unroll 4
        for (int k = 0; k < H; k++) {
            float w = U1[(H + k) * H + h];
#pragma unroll
            for (int jj = 0; jj < NT; jj++) acc[jj] = fmaf(av[jj][k], w, acc[jj]);
        }
#pragma unroll
        for (int jj = 0; jj < NT; jj++) hv[jj][h] = siluf(acc[jj]);
    }
    __syncthreads();
    {   // x += hv @ U2 + ub2
        float acc[NT];
        float b = upd_b2[l * H + h];
#pragma unroll
        for (int jj = 0; jj < NT; jj++) acc[jj] = b;
        const float* U2 = upd_w2 + l * H * H;
#pragma unroll 4
        for (int k = 0; k < H; k++) {
            float w = U2[k * H + h];
#pragma unroll
            for (int jj = 0; jj < NT; jj++) acc[jj] = fmaf(hv[jj][k], w, acc[jj]);
        }
#pragma unroll
        for (int jj = 0; jj < NT; jj++) g_x[(j0 + jj) * H + h] = xv[jj][h] + acc[jj];
    }
}

// segment-mean pool + output MLP
__global__ void k_out(const int* __restrict__ batch,
                      const float* __restrict__ ow1, const float* __restrict__ ob1,
                      const float* __restrict__ ow2, const float* __restrict__ ob2,
                      float* __restrict__ out) {
    int m = blockIdx.x, h = threadIdx.x;
    __shared__ float pv[H];
    __shared__ float hv[64];
    float s = 0.0f, c = 0.0f;
    for (int i = 0; i < NN; i++) {
        if (batch[i] == m) { s += g_x[i * H + h]; c += 1.0f; }
    }
    pv[h] = s / fmaxf(c, 1.0f);
    __syncthreads();
    if (h < 64) {
        float acc = ob1[h];
#pragma unroll 8
        for (int k = 0; k < H; k++) acc = fmaf(pv[k], ow1[k * 64 + h], acc);
        hv[h] = siluf(acc);
    }
    __syncthreads();
    if (h == 0) {
        float acc = ob2[0];
#pragma unroll
        for (int k = 0; k < 64; k++) acc = fmaf(hv[k], ow2[k], acc);
        out[m] = acc;
    }
}

extern "C" void kernel_launch(void* const* d_in, const int* in_sizes, int n_in,
                              void* d_out, int out_size) {
    const int*   an     = (const int*)  d_in[0];
    const float* pos    = (const float*)d_in[1];
    const int*   batch  = (const int*)  d_in[2];
    const float* embed  = (const float*)d_in[3];
    const float* msg_w1 = (const float*)d_in[4];
    const float* msg_b1 = (const float*)d_in[5];
    const float* msg_w2 = (const float*)d_in[6];
    const float* msg_b2 = (const float*)d_in[7];
    const float* upd_w1 = (const float*)d_in[8];
    const float* upd_b1 = (const float*)d_in[9];
    const float* upd_w2 = (const float*)d_in[10];
    const float* upd_b2 = (const float*)d_in[11];
    const float* ow1    = (const float*)d_in[12];
    const float* ob1    = (const float*)d_in[13];
    const float* ow2    = (const float*)d_in[14];
    const float* ob2    = (const float*)d_in[15];
    float* out = (float*)d_out;

    k_embed<<<NN, H>>>(an, embed);
    k_geo<<<(NN * NN + 255) / 256, 256>>>(pos);
    k_table<<<dim3(TBL + 1, L), H>>>(msg_w1);
    for (int l = 0; l < L; l++) {
        k_A<<<NN, H>>>(msg_w1, msg_b1, l);
        k_msg<<<dim3(NN / JT, IS), H>>>(msg_w1, l);
        k_upd<<<NN / NT, H>>>(msg_w2, msg_b2, upd_w1, upd_b1, upd_w2, upd_b2, l);
    }
    k_out<<<NMOL, H>>>(batch, ow1, ob1, ow2, ob2, out);
}

// round 6
// speedup vs baseline: 1.3450x; 1.3450x over previous
#include <cuda_runtime.h>

#define NN    512
#define H     128
#define L     4
#define NRBF  50
#define TBL   2048
#define NMOL  16
#define JT    8     // target nodes per msg block
#define IS    8     // i-range splits
#define NT    2     // nodes per update block

// ---- scratch (static __device__, no allocation) ----
__device__ float4 g_geo[NN * NN];            // [j][i] = (d_or_1e9, dirx, diry, dirz)
__device__ float2 g_tbl[L][TBL][H];          // (psi_l(idx), psi_l(idx+1)) per h
__device__ float  g_x[NN * H];
__device__ float  g_A[NN * H];               // x @ Wx + b1
__device__ float  g_S[NN * H];               // sum_i silu(pre[i,j])
__device__ float  g_deg[NN];                 // # valid neighbors of j (layer-invariant)
__device__ float  g_pool[NMOL * H];
__device__ float  g_cntm[NMOL];

__device__ __forceinline__ float tanhf_approx(float x) {
    float t;
    asm("tanh.approx.f32 %0, %1;" : "=f"(t) : "f"(x));
    return t;
}
__device__ __forceinline__ float siluf(float v) {
    float s = 0.5f * v;
    return fmaf(s, tanhf_approx(s), s);
}

// x = embed[clip(an)] ; zero deg/pool/cntm
__global__ void k_embed(const int* __restrict__ an, const float* __restrict__ embed) {
    int i = blockIdx.x, h = threadIdx.x;
    int a = an[i];
    a = a < 0 ? 0 : (a > 99 ? 99 : a);
    g_x[i * H + h] = embed[a * H + h];
    if (i < NMOL) g_pool[i * H + h] = 0.0f;
    if (h == 0) {
        g_deg[i] = 0.0f;
        if (i < NMOL) g_cntm[i] = 0.0f;
    }
}

// pair geometry + warp-aggregated degree count
__global__ void k_geo(const float* __restrict__ pos) {
    int t = blockIdx.x * blockDim.x + threadIdx.x;
    if (t >= NN * NN) return;
    int j = t / NN, i = t % NN;          // warp (32 consecutive i) shares j
    float dx = pos[i * 3 + 0] - pos[j * 3 + 0];
    float dy = pos[i * 3 + 1] - pos[j * 3 + 1];
    float dz = pos[i * 3 + 2] - pos[j * 3 + 2];
    float d  = sqrtf(dx * dx + dy * dy + dz * dz);
    float dm = fmaxf(d, 1e-8f);
    float inv = 1.0f / dm;
    bool valid = (d < 5.0f) && (i != j);
    g_geo[t] = make_float4(valid ? d : 1e9f, dx * inv, dy * inv, dz * inv);
    unsigned m = __ballot_sync(0xffffffffu, valid);
    if ((threadIdx.x & 31) == 0)
        atomicAdd(&g_deg[j], (float)__popc(m));
}

// psi tables, interleaved (psi(idx), psi(idx+1))
__global__ void k_table(const float* __restrict__ msg_w1) {
    int idx = blockIdx.x;        // 0..TBL-1
    int l   = blockIdx.y;
    int h   = threadIdx.x;
    __shared__ float e0[NRBF], e1[NRBF];
    float g  = 5.0f / (float)TBL;
    float d0 = (float)idx * g;
    float d1 = (float)(idx + 1) * g;
    if (h < NRBF) {
        float c  = 5.0f * (float)h / (float)(NRBF - 1);
        float u0 = d0 - c, u1 = d1 - c;
        e0[h] = expf(-u0 * u0 * 50.0f);
        e1[h] = expf(-u1 * u1 * 50.0f);
    }
    __syncthreads();
    const float* Wr = msg_w1 + l * 181 * H + H * H;   // rows [H, H+50)
    float s0 = 0.0f, s1 = 0.0f;
#pragma unroll
    for (int k = 0; k < NRBF; k++) {
        float w = Wr[k * H + h];
        s0 = fmaf(e0[k], w, s0);
        s1 = fmaf(e1[k], w, s1);
    }
    g_tbl[l][idx][h] = make_float2(s0, s1);
}

// A = x @ Wx_l + b1_l ; zero S
__global__ void k_A(const float* __restrict__ msg_w1, const float* __restrict__ msg_b1, int l) {
    int i = blockIdx.x, h = threadIdx.x;
    __shared__ float xv[H];
    xv[h] = g_x[i * H + h];
    __syncthreads();
    const float* Wx = msg_w1 + l * 181 * H;
    float acc = msg_b1[l * H + h];
#pragma unroll 8
    for (int k = 0; k < H; k++)
        acc = fmaf(xv[k], Wx[k * H + h], acc);
    g_A[i * H + h] = acc;
    g_S[i * H + h] = 0.0f;
}

// branchless message pass: S[j,h] += silu(A[i,h] + psi(d)[h] + dir.Wd[:,h]) * valid
__global__ void k_msg(const float* __restrict__ msg_w1, int l) {
    int j0 = blockIdx.x * JT;
    int i0 = blockIdx.y * (NN / IS);
    int h  = threadIdx.x;
    const float* Wd = msg_w1 + l * 181 * H + (H + NRBF) * H;
    float wd0 = Wd[0 * H + h], wd1 = Wd[1 * H + h], wd2 = Wd[2 * H + h];
    const float2* __restrict__ tbl = &g_tbl[l][0][0];

    float acc[JT];
#pragma unroll
    for (int jj = 0; jj < JT; jj++) acc[jj] = 0.0f;

    for (int i = i0; i < i0 + NN / IS; i++) {
        float a = __ldg(&g_A[i * H + h]);
#pragma unroll
        for (int jj = 0; jj < JT; jj++) {
            float4 w = __ldg(&g_geo[(j0 + jj) * NN + i]);
            float dcl = fminf(w.x, 4.999f);
            float t   = dcl * ((float)TBL / 5.0f);
            int   t0  = (int)t;
            float f   = t - (float)t0;
            float2 T  = __ldg(&tbl[t0 * H + h]);
            float pre = fmaf(f, T.y - T.x, a + T.x);
            pre = fmaf(w.y, wd0, pre);
            pre = fmaf(w.z, wd1, pre);
            pre = fmaf(w.w, wd2, pre);
            float s  = (w.x < 5.0f) ? 0.5f * pre : 0.0f;   // mask; tanh(0)=0
            float th = tanhf_approx(s);
            acc[jj] = fmaf(s, th, acc[jj] + s);            // += silu
        }
    }
#pragma unroll
    for (int jj = 0; jj < JT; jj++)
        atomicAdd(&g_S[(j0 + jj) * H + h], acc[jj]);
}

// aggr = S@W2 + deg*b2 ; x += silu([x,aggr]@U1 + ub1) @ U2 + ub2
__global__ void k_upd(const float* __restrict__ msg_w2, const float* __restrict__ msg_b2,
                      const float* __restrict__ upd_w1, const float* __restrict__ upd_b1,
                      const float* __restrict__ upd_w2, const float* __restrict__ upd_b2, int l) {
    int j0 = blockIdx.x * NT;
    int h  = threadIdx.x;
    __shared__ float sv[NT][H], xv[NT][H], av[NT][H], hv[NT][H];
#pragma unroll
    for (int jj = 0; jj < NT; jj++) {
        sv[jj][h] = g_S[(j0 + jj) * H + h];
        xv[jj][h] = g_x[(j0 + jj) * H + h];
    }
    __syncthreads();
    {
        float b = msg_b2[l * H + h];
        float acc[NT];
#pragma unroll
        for (int jj = 0; jj < NT; jj++) acc[jj] = g_deg[j0 + jj] * b;
        const float* W2 = msg_w2 + l * H * H;
#pragma unroll 8
        for (int k = 0; k < H; k++) {
            float w = W2[k * H + h];
#pragma unroll
            for (int jj = 0; jj < NT; jj++) acc[jj] = fmaf(sv[jj][k], w, acc[jj]);
        }
#pragma unroll
        for (int jj = 0; jj < NT; jj++) av[jj][h] = acc[jj];
    }
    __syncthreads();
    {
        float acc[NT];
        float b = upd_b1[l * H + h];
#pragma unroll
        for (int jj = 0; jj < NT; jj++) acc[jj] = b;
        const float* U1 = upd_w1 + l * 2 * H * H;
#pragma unroll 8
        for (int k = 0; k < H; k++) {
            float w = U1[k * H + h];
#pragma unroll
            for (int jj = 0; jj < NT; jj++) acc[jj] = fmaf(xv[jj][k], w, acc[jj]);
        }
#pragma unroll 8
        for (int k = 0; k < H; k++) {
            float w = U1[(H + k) * H + h];
#pragma unroll
            for (int jj = 0; jj < NT; jj++) acc[jj] = fmaf(av[jj][k], w, acc[jj]);
        }
#pragma unroll
        for (int jj = 0; jj < NT; jj++) hv[jj][h] = siluf(acc[jj]);
    }
    __syncthreads();
    {
        float acc[NT];
        float b = upd_b2[l * H + h];
#pragma unroll
        for (int jj = 0; jj < NT; jj++) acc[jj] = b;
        const float* U2 = upd_w2 + l * H * H;
#pragma unroll 8
        for (int k = 0; k < H; k++) {
            float w = U2[k * H + h];
#pragma unroll
            for (int jj = 0; jj < NT; jj++) acc[jj] = fmaf(hv[jj][k], w, acc[jj]);
        }
#pragma unroll
        for (int jj = 0; jj < NT; jj++) g_x[(j0 + jj) * H + h] = xv[jj][h] + acc[jj];
    }
}

// parallel segment-sum pooling
__global__ void k_pool(const int* __restrict__ batch) {
    int i = blockIdx.x, h = threadIdx.x;
    int b = batch[i];
    atomicAdd(&g_pool[b * H + h], g_x[i * H + h]);
    if (h == 0) atomicAdd(&g_cntm[b], 1.0f);
}

// mean + output MLP
__global__ void k_head(const float* __restrict__ ow1, const float* __restrict__ ob1,
                       const float* __restrict__ ow2, const float* __restrict__ ob2,
                       float* __restrict__ out) {
    int m = blockIdx.x, h = threadIdx.x;
    __shared__ float pv[H];
    __shared__ float hv[64];
    pv[h] = g_pool[m * H + h] / fmaxf(g_cntm[m], 1.0f);
    __syncthreads();
    if (h < 64) {
        float acc = ob1[h];
#pragma unroll 8
        for (int k = 0; k < H; k++) acc = fmaf(pv[k], ow1[k * 64 + h], acc);
        float s = 0.5f * acc;
        hv[h] = fmaf(s, tanhf_approx(s), s);
    }
    __syncthreads();
    if (h == 0) {
        float acc = ob2[0];
#pragma unroll
        for (int k = 0; k < 64; k++) acc = fmaf(hv[k], ow2[k], acc);
        out[m] = acc;
    }
}

extern "C" void kernel_launch(void* const* d_in, const int* in_sizes, int n_in,
                              void* d_out, int out_size) {
    const int*   an     = (const int*)  d_in[0];
    const float* pos    = (const float*)d_in[1];
    const int*   batch  = (const int*)  d_in[2];
    const float* embed  = (const float*)d_in[3];
    const float* msg_w1 = (const float*)d_in[4];
    const float* msg_b1 = (const float*)d_in[5];
    const float* msg_w2 = (const float*)d_in[6];
    const float* msg_b2 = (const float*)d_in[7];
    const float* upd_w1 = (const float*)d_in[8];
    const float* upd_b1 = (const float*)d_in[9];
    const float* upd_w2 = (const float*)d_in[10];
    const float* upd_b2 = (const float*)d_in[11];
    const float* ow1    = (const float*)d_in[12];
    const float* ob1    = (const float*)d_in[13];
    const float* ow2    = (const float*)d_in[14];
    const float* ob2    = (const float*)d_in[15];
    float* out = (float*)d_out;

    k_embed<<<NN, H>>>(an, embed);
    k_geo<<<(NN * NN + 255) / 256, 256>>>(pos);
    k_table<<<dim3(TBL, L), H>>>(msg_w1);
    for (int l = 0; l < L; l++) {
        k_A<<<NN, H>>>(msg_w1, msg_b1, l);
        k_msg<<<dim3(NN / JT, IS), H>>>(msg_w1, l);
        k_upd<<<NN / NT, H>>>(msg_w2, msg_b2, upd_w1, upd_b1, upd_w2, upd_b2, l);
    }
    k_pool<<<NN, H>>>(batch);
    k_head<<<NMOL, H>>>(ow1, ob1, ow2, ob2, out);
}